// round 8
// baseline (speedup 1.0000x reference)
#include <cuda_runtime.h>
#include <cuda_fp16.h>
#include <cstdint>
#include <math.h>

// Problem constants
#define BATCH 4
#define SEQ   2048
#define DIM   768
#define HEADS 12
#define DHEAD 64
#define INNER 768
#define ROWS  (BATCH * SEQ)        // 8192
#define QKV_N (3 * INNER)          // 2304

// Scratch (allocation-free: __device__ globals) — all intermediates fp16
__device__ __align__(256) __half g_xn[ROWS * DIM];
__device__ __align__(256) __half g_qkv[ROWS * QKV_N];
__device__ __align__(256) __half g_attn[ROWS * INNER];
__device__ __align__(256) __half g_wtq[QKV_N * DIM];   // W_qkv^T [N,K]
__device__ __align__(256) __half g_wto[DIM * INNER];   // W_out^T [N,K]

// ---------------------------------------------------------------------------
// helpers (plain sm_80-era PTX — compiles for bare compute_103)
// ---------------------------------------------------------------------------
__device__ __forceinline__ uint32_t smem_u32(const void* p) {
    uint32_t a;
    asm("{ .reg .u64 t; cvta.to.shared.u64 t, %1; cvt.u32.u64 %0, t; }"
        : "=r"(a) : "l"(p));
    return a;
}

__device__ __forceinline__ void cp16(uint32_t dst, const void* src) {
    asm volatile("cp.async.cg.shared.global [%0], [%1], 16;"
                 :: "r"(dst), "l"(src));
}
#define CP_COMMIT() asm volatile("cp.async.commit_group;")
#define CP_WAIT0()  asm volatile("cp.async.wait_group 0;")
#define CP_WAIT1()  asm volatile("cp.async.wait_group 1;")

__device__ __forceinline__ void ldm4(uint32_t r[4], uint32_t a) {
    asm volatile("ldmatrix.sync.aligned.m8n8.x4.shared.b16 {%0,%1,%2,%3}, [%4];"
        : "=r"(r[0]), "=r"(r[1]), "=r"(r[2]), "=r"(r[3]) : "r"(a));
}
__device__ __forceinline__ void ldm4t(uint32_t r[4], uint32_t a) {
    asm volatile("ldmatrix.sync.aligned.m8n8.x4.trans.shared.b16 {%0,%1,%2,%3}, [%4];"
        : "=r"(r[0]), "=r"(r[1]), "=r"(r[2]), "=r"(r[3]) : "r"(a));
}

__device__ __forceinline__ void mma16(float c[4], const uint32_t a[4],
                                      uint32_t b0, uint32_t b1) {
    asm volatile(
        "mma.sync.aligned.m16n8k16.row.col.f32.f16.f16.f32 "
        "{%0,%1,%2,%3}, {%4,%5,%6,%7}, {%8,%9}, {%0,%1,%2,%3};"
        : "+f"(c[0]), "+f"(c[1]), "+f"(c[2]), "+f"(c[3])
        : "r"(a[0]), "r"(a[1]), "r"(a[2]), "r"(a[3]), "r"(b0), "r"(b1));
}

__device__ __forceinline__ float ex2(float x) {
    float r;
    asm("ex2.approx.f32 %0, %1;" : "=f"(r) : "f"(x));
    return r;
}

// ---------------------------------------------------------------------------
// Kernel 0: transpose W[K,N] -> Wt[N,K] (fp16 out)
// ---------------------------------------------------------------------------
__global__ __launch_bounds__(256) void transpose_k(
    const float* __restrict__ W, __half* __restrict__ Wt, int R, int Ccols)
{
    __shared__ float t[32][33];
    const int c0 = blockIdx.x * 32, r0 = blockIdx.y * 32;
    const int x = threadIdx.x & 31, y = threadIdx.x >> 5;
    #pragma unroll
    for (int i = 0; i < 32; i += 8)
        t[y + i][x] = W[(size_t)(r0 + y + i) * Ccols + c0 + x];
    __syncthreads();
    #pragma unroll
    for (int i = 0; i < 32; i += 8)
        Wt[(size_t)(c0 + y + i) * R + r0 + x] = __float2half_rn(t[x][y + i]);
}

// ---------------------------------------------------------------------------
// Kernel 1: LayerNorm (fp16 out)
// ---------------------------------------------------------------------------
__global__ __launch_bounds__(256) void ln_kernel(
    const float* __restrict__ x, const float* __restrict__ g,
    const float* __restrict__ b, __half* __restrict__ xn)
{
    const int row = blockIdx.x;
    const int tid = threadIdx.x;
    const float* xr = x + (size_t)row * DIM;

    float v0 = xr[tid];
    float v1 = xr[tid + 256];
    float v2 = xr[tid + 512];
    float s  = v0 + v1 + v2;
    float ss = v0 * v0 + v1 * v1 + v2 * v2;

    #pragma unroll
    for (int m = 16; m; m >>= 1) {
        s  += __shfl_xor_sync(0xffffffffu, s, m);
        ss += __shfl_xor_sync(0xffffffffu, ss, m);
    }
    __shared__ float shs[8], shss[8], stat[2];
    const int w = tid >> 5, l = tid & 31;
    if (l == 0) { shs[w] = s; shss[w] = ss; }
    __syncthreads();
    if (tid == 0) {
        float S = 0.f, SS = 0.f;
        #pragma unroll
        for (int i = 0; i < 8; i++) { S += shs[i]; SS += shss[i]; }
        float mean = S * (1.f / DIM);
        float var  = SS * (1.f / DIM) - mean * mean;
        stat[0] = mean;
        stat[1] = rsqrtf(var + 1e-5f);
    }
    __syncthreads();
    const float mean = stat[0], rstd = stat[1];
    __half* xo = xn + (size_t)row * DIM;
    xo[tid]       = __float2half_rn((v0 - mean) * rstd * g[tid]       + b[tid]);
    xo[tid + 256] = __float2half_rn((v1 - mean) * rstd * g[tid + 256] + b[tid + 256]);
    xo[tid + 512] = __float2half_rn((v2 - mean) * rstd * g[tid + 512] + b[tid + 512]);
}

// ---------------------------------------------------------------------------
// Kernel 2/4: fp16 mma GEMM.  C[M,N] = A[M,K] @ Bt[N,K]^T + bias
// Block 256x128, 8 warps (4m x 2n), warp tile 64x64, BK=32,
// 3-stage cp.async ring, ONE __syncthreads per K-chunk.
// SMEM row stride 40 halfs (80B) — conflict-free ldmatrix patterns.
// ---------------------------------------------------------------------------
#define GSTR 40
#define G_AS  (256 * GSTR)            // halfs per A stage
#define G_BS  (128 * GSTR)            // halfs per B stage
#define G_SMEM ((3 * G_AS + 3 * G_BS) * 2)   // 92160 bytes

__global__ __launch_bounds__(256) void gemm_h(
    const __half* __restrict__ A, const __half* __restrict__ Bt,
    const float* __restrict__ bias, void* __restrict__ Cout,
    int N, int K, int half_out)
{
    extern __shared__ __half gsm[];
    __half* As = gsm;                 // 3 stages of 256x40
    __half* Bs = gsm + 3 * G_AS;      // 3 stages of 128x40

    const int tid  = threadIdx.x;
    const int lane = tid & 31;
    const int wid  = tid >> 5;
    const int wm = (wid & 3) * 64;    // warp m-offset (0,64,128,192)
    const int wn = (wid >> 2) * 64;   // warp n-offset (0,64)
    const int qr = lane >> 2, qc = lane & 3;
    const int bx = blockIdx.x, by = blockIdx.y;

    const __half* Ab = A  + (size_t)by * 256 * K;
    const __half* Bb = Bt + (size_t)bx * 128 * K;

    const int lr = tid >> 2;          // loader row base
    const int lc = (tid & 3) * 8;     // loader col (halfs)

    // stage loader: A 256x32 (4 chunks/thread), B 128x32 (2 chunks/thread)
    auto load_stage = [&](int st, int k0) {
        uint32_t au = smem_u32(As + st * G_AS);
        uint32_t bu = smem_u32(Bs + st * G_BS);
        #pragma unroll
        for (int j = 0; j < 4; j++) {
            const int r = lr + j * 64;
            cp16(au + (uint32_t)(r * GSTR + lc) * 2, Ab + (size_t)r * K + k0 + lc);
        }
        #pragma unroll
        for (int j = 0; j < 2; j++) {
            const int r = lr + j * 64;
            cp16(bu + (uint32_t)(r * GSTR + lc) * 2, Bb + (size_t)r * K + k0 + lc);
        }
        CP_COMMIT();
    };

    float acc[4][8][4];
    #pragma unroll
    for (int mi = 0; mi < 4; mi++)
        #pragma unroll
        for (int ni = 0; ni < 8; ni++)
            #pragma unroll
            for (int j = 0; j < 4; j++) acc[mi][ni][j] = 0.f;

    const int NC = K / 32;            // 24

    load_stage(0, 0);
    load_stage(1, 32);

    for (int kc = 0; kc < NC; kc++) {
        if (kc + 2 < NC) CP_WAIT1(); else CP_WAIT0();
        __syncthreads();
        if (kc + 2 < NC) load_stage((kc + 2) % 3, (kc + 2) * 32);

        const int st = kc % 3;
        const uint32_t a_base = smem_u32(As + st * G_AS);
        const uint32_t b_base = smem_u32(Bs + st * G_BS);

        #pragma unroll
        for (int ks = 0; ks < 2; ks++) {
            const int k0 = ks * 16;
            uint32_t af[4][4];
            #pragma unroll
            for (int mi = 0; mi < 4; mi++) {
                const uint32_t ad = a_base +
                    (uint32_t)((wm + mi * 16 + (lane & 15)) * GSTR
                               + k0 + ((lane >> 4) << 3)) * 2;
                ldm4(af[mi], ad);
            }
            #pragma unroll
            for (int np = 0; np < 4; np++) {
                uint32_t bf[4];
                const uint32_t bd = b_base +
                    (uint32_t)((wn + np * 16 + (lane & 7) + ((lane >> 4) << 3)) * GSTR
                               + k0 + (((lane >> 3) & 1) << 3)) * 2;
                ldm4(bf, bd);
                #pragma unroll
                for (int mi = 0; mi < 4; mi++) {
                    mma16(acc[mi][2 * np],     af[mi], bf[0], bf[1]);
                    mma16(acc[mi][2 * np + 1], af[mi], bf[2], bf[3]);
                }
            }
        }
    }

    // ---- epilogue
    const int cb = bx * 128 + wn;
    if (half_out) {
        __half* C = (__half*)Cout;
        #pragma unroll
        for (int mi = 0; mi < 4; mi++)
            #pragma unroll
            for (int hf = 0; hf < 2; hf++) {
                const int row = by * 256 + wm + mi * 16 + qr + hf * 8;
                __half* Cp = C + (size_t)row * N + cb;
                #pragma unroll
                for (int ni = 0; ni < 8; ni++) {
                    const int c = ni * 8 + 2 * qc;
                    *(__half2*)(Cp + c) = __floats2half2_rn(
                        acc[mi][ni][hf * 2 + 0] + bias[cb + c],
                        acc[mi][ni][hf * 2 + 1] + bias[cb + c + 1]);
                }
            }
    } else {
        float* C = (float*)Cout;
        #pragma unroll
        for (int mi = 0; mi < 4; mi++)
            #pragma unroll
            for (int hf = 0; hf < 2; hf++) {
                const int row = by * 256 + wm + mi * 16 + qr + hf * 8;
                float* Cp = C + (size_t)row * N + cb;
                #pragma unroll
                for (int ni = 0; ni < 8; ni++) {
                    const int c = ni * 8 + 2 * qc;
                    float2 v;
                    v.x = acc[mi][ni][hf * 2 + 0] + bias[cb + c];
                    v.y = acc[mi][ni][hf * 2 + 1] + bias[cb + c + 1];
                    *(float2*)(Cp + c) = v;
                }
            }
    }
}

// ---------------------------------------------------------------------------
// Kernel 3: fp16 flash attention.  BR=128, BC=64, d=64.  8 warps; each warp
// owns 16 query rows (warp-local online softmax, exp2 domain).
// 3-stage cp.async K/V ring, ONE __syncthreads per tile.
// ---------------------------------------------------------------------------
#define FSTR 72
#define F_Q   (128 * FSTR)
#define F_KV  (64 * FSTR)
#define F_SMEM ((2 * F_Q + 6 * F_KV) * 2)   // 92160 bytes
#define SC_L2E 0.18033688011112042f          // 0.125 * log2(e)

__global__ __launch_bounds__(256) void flash_h(
    const __half* __restrict__ qkv, __half* __restrict__ out)
{
    extern __shared__ __half fs[];
    __half* Qs = fs;                       // 128 x FSTR
    __half* Ps = fs + F_Q;                 // 128 x FSTR
    __half* Ks = fs + 2 * F_Q;             // 3 stages x 64 x FSTR
    __half* Vs = fs + 2 * F_Q + 3 * F_KV;  // 3 stages x 64 x FSTR

    const int tid  = threadIdx.x;
    const int lane = tid & 31;
    const int wid  = tid >> 5;             // 0..7
    const int qr = lane >> 2, qc = lane & 3;
    const int m0 = wid * 16;

    const int qt = blockIdx.x;             // 0..15 (128-row query tiles)
    const int bh = blockIdx.y;             // 0..47
    const int bb = bh / HEADS, h = bh % HEADS;

    const __half* base = qkv + (size_t)bb * SEQ * QKV_N;
    const __half* qb = base + h * DHEAD;
    const __half* kb = base + INNER + h * DHEAD;
    const __half* vb = base + 2 * INNER + h * DHEAD;

    const uint32_t q_u = smem_u32(Qs);
    const uint32_t p_u = smem_u32(Ps);

    const int lr = tid >> 3;               // 0..31 loader row base
    const int lc8 = (tid & 7) * 8;

    auto load_kv = [&](int st, int t) {
        uint32_t ku = smem_u32(Ks + st * F_KV);
        uint32_t vu = smem_u32(Vs + st * F_KV);
        #pragma unroll
        for (int j = 0; j < 2; j++) {
            const int r = lr + j * 32;
            const size_t off = (size_t)(t * 64 + r) * QKV_N + lc8;
            cp16(ku + (uint32_t)(r * FSTR + lc8) * 2, kb + off);
            cp16(vu + (uint32_t)(r * FSTR + lc8) * 2, vb + off);
        }
        CP_COMMIT();
    };

    // prologue: group0 = Q(128x64) + K/V stage0 ; group1 = K/V stage1
    #pragma unroll
    for (int j = 0; j < 4; j++) {
        const int r = lr + j * 32;
        cp16(q_u + (uint32_t)(r * FSTR + lc8) * 2,
             qb + (size_t)(qt * 128 + r) * QKV_N + lc8);
    }
    {
        uint32_t ku = smem_u32(Ks);
        uint32_t vu = smem_u32(Vs);
        #pragma unroll
        for (int j = 0; j < 2; j++) {
            const int r = lr + j * 32;
            const size_t off = (size_t)r * QKV_N + lc8;
            cp16(ku + (uint32_t)(r * FSTR + lc8) * 2, kb + off);
            cp16(vu + (uint32_t)(r * FSTR + lc8) * 2, vb + off);
        }
        CP_COMMIT();
    }
    load_kv(1, 1);

    float mrow[2] = {-1e30f, -1e30f};
    float lrow[2] = {0.f, 0.f};
    float o[8][4];
    #pragma unroll
    for (int ni = 0; ni < 8; ni++)
        #pragma unroll
        for (int j = 0; j < 4; j++) o[ni][j] = 0.f;

    uint32_t qf[4][4];
    const int NT = SEQ / 64;

    for (int t = 0; t < NT; t++) {
        if (t + 2 < NT) CP_WAIT1(); else CP_WAIT0();
        __syncthreads();
        if (t + 2 < NT) load_kv((t + 2) % 3, t + 2);

        const int st = t % 3;
        const uint32_t k_b = smem_u32(Ks + st * F_KV);
        const uint32_t v_b = smem_u32(Vs + st * F_KV);

        if (t == 0) {
            #pragma unroll
            for (int ks = 0; ks < 4; ks++)
                ldm4(qf[ks], q_u + (uint32_t)((m0 + (lane & 15)) * FSTR
                         + ks * 16 + ((lane >> 4) << 3)) * 2);
        }

        // ---- S = Q @ K^T ----
        float s[8][4];
        #pragma unroll
        for (int ni = 0; ni < 8; ni++)
            #pragma unroll
            for (int j = 0; j < 4; j++) s[ni][j] = 0.f;

        #pragma unroll
        for (int ks = 0; ks < 4; ks++) {
            const int k0 = ks * 16;
            #pragma unroll
            for (int np = 0; np < 4; np++) {
                uint32_t bf[4];
                const uint32_t bd = k_b +
                    (uint32_t)((np * 16 + (lane & 7) + ((lane >> 4) << 3)) * FSTR
                               + k0 + (((lane >> 3) & 1) << 3)) * 2;
                ldm4(bf, bd);
                mma16(s[2 * np],     qf[ks], bf[0], bf[1]);
                mma16(s[2 * np + 1], qf[ks], bf[2], bf[3]);
            }
        }

        // ---- online softmax in exp2 domain (scale folded) ----
        #pragma unroll
        for (int ni = 0; ni < 8; ni++)
            #pragma unroll
            for (int j = 0; j < 4; j++) s[ni][j] *= SC_L2E;

        float mx0 = -1e30f, mx1 = -1e30f;
        #pragma unroll
        for (int ni = 0; ni < 8; ni++) {
            mx0 = fmaxf(mx0, fmaxf(s[ni][0], s[ni][1]));
            mx1 = fmaxf(mx1, fmaxf(s[ni][2], s[ni][3]));
        }
        mx0 = fmaxf(mx0, __shfl_xor_sync(0xffffffffu, mx0, 1));
        mx0 = fmaxf(mx0, __shfl_xor_sync(0xffffffffu, mx0, 2));
        mx1 = fmaxf(mx1, __shfl_xor_sync(0xffffffffu, mx1, 1));
        mx1 = fmaxf(mx1, __shfl_xor_sync(0xffffffffu, mx1, 2));

        const float mn0 = fmaxf(mrow[0], mx0);
        const float mn1 = fmaxf(mrow[1], mx1);
        const float al0 = ex2(mrow[0] - mn0);
        const float al1 = ex2(mrow[1] - mn1);
        mrow[0] = mn0; mrow[1] = mn1;

        float sum0 = 0.f, sum1 = 0.f;
        #pragma unroll
        for (int ni = 0; ni < 8; ni++) {
            s[ni][0] = ex2(s[ni][0] - mn0); sum0 += s[ni][0];
            s[ni][1] = ex2(s[ni][1] - mn0); sum0 += s[ni][1];
            s[ni][2] = ex2(s[ni][2] - mn1); sum1 += s[ni][2];
            s[ni][3] = ex2(s[ni][3] - mn1); sum1 += s[ni][3];
        }
        sum0 += __shfl_xor_sync(0xffffffffu, sum0, 1);
        sum0 += __shfl_xor_sync(0xffffffffu, sum0, 2);
        sum1 += __shfl_xor_sync(0xffffffffu, sum1, 1);
        sum1 += __shfl_xor_sync(0xffffffffu, sum1, 2);
        lrow[0] = lrow[0] * al0 + sum0;
        lrow[1] = lrow[1] * al1 + sum1;

        #pragma unroll
        for (int ni = 0; ni < 8; ni++) {
            o[ni][0] *= al0; o[ni][1] *= al0;
            o[ni][2] *= al1; o[ni][3] *= al1;
        }

        // ---- P (C-frag fp32) -> warp-private SMEM rows as fp16 ----
        #pragma unroll
        for (int ni = 0; ni < 8; ni++) {
            const int c = ni * 8 + 2 * qc;
            *(__half2*)(Ps + (m0 + qr) * FSTR + c) =
                __floats2half2_rn(s[ni][0], s[ni][1]);
            *(__half2*)(Ps + (m0 + qr + 8) * FSTR + c) =
                __floats2half2_rn(s[ni][2], s[ni][3]);
        }
        __syncwarp();

        // ---- O += P @ V  (V via ldmatrix.trans) ----
        #pragma unroll
        for (int ks = 0; ks < 4; ks++) {
            uint32_t pf[4];
            ldm4(pf, p_u + (uint32_t)((m0 + (lane & 15)) * FSTR
                     + ks * 16 + ((lane >> 4) << 3)) * 2);
            #pragma unroll
            for (int np = 0; np < 4; np++) {
                uint32_t vf[4];
                const uint32_t vd = v_b +
                    (uint32_t)((ks * 16 + (lane & 7) + (((lane >> 3) & 1) << 3)) * FSTR
                               + np * 16 + ((lane >> 4) << 3)) * 2;
                ldm4t(vf, vd);
                mma16(o[2 * np],     pf, vf[0], vf[1]);
                mma16(o[2 * np + 1], pf, vf[2], vf[3]);
            }
        }
        __syncwarp();
    }

    // ---- normalize + store (half) into [b, n, h*64 + d] ----
    const float inv0 = 1.f / lrow[0];
    const float inv1 = 1.f / lrow[1];
    const size_t n0 = (size_t)bb * SEQ + qt * 128 + m0 + qr;
    #pragma unroll
    for (int ni = 0; ni < 8; ni++) {
        const int c = h * DHEAD + ni * 8 + 2 * qc;
        *(__half2*)(out + n0 * INNER + c) =
            __floats2half2_rn(o[ni][0] * inv0, o[ni][1] * inv0);
        *(__half2*)(out + (n0 + 8) * INNER + c) =
            __floats2half2_rn(o[ni][2] * inv1, o[ni][3] * inv1);
    }
}

// ---------------------------------------------------------------------------
extern "C" void kernel_launch(void* const* d_in, const int* in_sizes, int n_in,
                              void* d_out, int out_size)
{
    const float* x     = (const float*)d_in[0];
    const float* ln_g  = (const float*)d_in[1];
    const float* ln_b  = (const float*)d_in[2];
    const float* W_qkv = (const float*)d_in[3];
    const float* b_qkv = (const float*)d_in[4];
    const float* W_out = (const float*)d_in[5];
    const float* b_out = (const float*)d_in[6];
    float* out = (float*)d_out;

    __half *xn, *qkv, *attn, *wtq, *wto;
    cudaGetSymbolAddress((void**)&xn,   g_xn);
    cudaGetSymbolAddress((void**)&qkv,  g_qkv);
    cudaGetSymbolAddress((void**)&attn, g_attn);
    cudaGetSymbolAddress((void**)&wtq,  g_wtq);
    cudaGetSymbolAddress((void**)&wto,  g_wto);

    cudaFuncSetAttribute(gemm_h, cudaFuncAttributeMaxDynamicSharedMemorySize,
                         G_SMEM);
    cudaFuncSetAttribute(flash_h, cudaFuncAttributeMaxDynamicSharedMemorySize,
                         F_SMEM);

    // 0) transpose weights to [N,K] fp16
    transpose_k<<<dim3(QKV_N / 32, DIM / 32), 256>>>(W_qkv, wtq, DIM, QKV_N);
    transpose_k<<<dim3(DIM / 32, INNER / 32), 256>>>(W_out, wto, INNER, DIM);

    // 1) LayerNorm -> fp16
    ln_kernel<<<ROWS, 256>>>(x, ln_g, ln_b, xn);

    // 2) QKV projection (fp16 mma, half out)
    gemm_h<<<dim3(QKV_N / 128, ROWS / 256), 256, G_SMEM>>>(
        xn, wtq, b_qkv, qkv, QKV_N, DIM, 1);

    // 3) attention (fp16 flash, half out)
    flash_h<<<dim3(SEQ / 128, BATCH * HEADS), 256, F_SMEM>>>(qkv, attn);

    // 4) output projection (fp16 mma, fp32 out)
    gemm_h<<<dim3(DIM / 128, ROWS / 256), 256, G_SMEM>>>(
        attn, wto, b_out, out, DIM, INNER, 0);
}